// round 11
// baseline (speedup 1.0000x reference)
#include <cuda_runtime.h>
#include <cstdint>

#define DIM 1024
#define NQ 4096
#define NKV 4096
#define NH 16
#define HD 64
#define ATT_SCALE 0.125f  // HD^-0.5

// Scratch (allocation-free rule: __device__ globals)
__device__ float g_Q[NQ * DIM];
__device__ float g_K[NKV * DIM];
__device__ float g_V[NKV * DIM];
__device__ float g_AO[NQ * DIM];

static __device__ __forceinline__ float to_tf32(float x) {
    float r; asm("cvt.rna.tf32.f32 %0, %1;" : "=f"(r) : "f"(x)); return r;
}

static __device__ __forceinline__ void mma_tf32(
    float* c, const float a0, const float a1, const float a2, const float a3,
    const float b0, const float b1) {
    asm volatile(
        "mma.sync.aligned.m16n8k8.row.col.f32.tf32.tf32.f32 "
        "{%0,%1,%2,%3}, {%4,%5,%6,%7}, {%8,%9}, {%0,%1,%2,%3};"
        : "+f"(c[0]), "+f"(c[1]), "+f"(c[2]), "+f"(c[3])
        : "f"(a0), "f"(a1), "f"(a2), "f"(a3), "f"(b0), "f"(b1));
}

// ---------------------------------------------------------------------------
// 3xTF32 mma.sync GEMM: C = X @ W^T + bias  (unchanged — passing, occ 2)
// ---------------------------------------------------------------------------
#define SASTRIDE 36
#define GEMM_SMEM_BYTES (4 * 128 * SASTRIDE * 4)

__global__ __launch_bounds__(256, 2)
void gemm_tc(const float* __restrict__ Xin, int src_tag,
             const float* __restrict__ W,
             const float* __restrict__ bias,
             float* __restrict__ Cout, int dst_tag) {
    extern __shared__ float smf[];
    float* Ah = smf;
    float* Al = Ah + 128 * SASTRIDE;
    float* Bh = Al + 128 * SASTRIDE;
    float* Bl = Bh + 128 * SASTRIDE;

    const float* X = (src_tag == 2) ? g_AO : Xin;
    float* C;
    switch (dst_tag) {
        case 0: C = g_Q; break;
        case 1: C = g_K; break;
        case 2: C = g_V; break;
        default: C = Cout; break;
    }

    const int tid = threadIdx.x;
    const int wid = tid >> 5;
    const int lane = tid & 31;
    const int wr = wid >> 2;
    const int wc = wid & 3;
    const int tr = lane >> 2;
    const int tk = lane & 3;
    const int row0 = blockIdx.y * 128;
    const int col0 = blockIdx.x * 128;

    float acc[4][4][4];
#pragma unroll
    for (int i = 0; i < 4; i++)
#pragma unroll
        for (int j = 0; j < 4; j++)
#pragma unroll
            for (int k = 0; k < 4; k++) acc[i][j][k] = 0.f;

    for (int kb = 0; kb < DIM; kb += 32) {
        __syncthreads();
#pragma unroll
        for (int j = 0; j < 4; j++) {
            const int q = tid + j * 256;
            const int r = q >> 3;
            const int c4 = (q & 7) * 4;
            float4 xv = *(const float4*)&X[(size_t)(row0 + r) * DIM + kb + c4];
            float4 wv = *(const float4*)&W[(size_t)(col0 + r) * DIM + kb + c4];
            float4 h, l;
            h.x = to_tf32(xv.x); l.x = to_tf32(xv.x - h.x);
            h.y = to_tf32(xv.y); l.y = to_tf32(xv.y - h.y);
            h.z = to_tf32(xv.z); l.z = to_tf32(xv.z - h.z);
            h.w = to_tf32(xv.w); l.w = to_tf32(xv.w - h.w);
            *(float4*)&Ah[r * SASTRIDE + c4] = h;
            *(float4*)&Al[r * SASTRIDE + c4] = l;
            h.x = to_tf32(wv.x); l.x = to_tf32(wv.x - h.x);
            h.y = to_tf32(wv.y); l.y = to_tf32(wv.y - h.y);
            h.z = to_tf32(wv.z); l.z = to_tf32(wv.z - h.z);
            h.w = to_tf32(wv.w); l.w = to_tf32(wv.w - h.w);
            *(float4*)&Bh[r * SASTRIDE + c4] = h;
            *(float4*)&Bl[r * SASTRIDE + c4] = l;
        }
        __syncthreads();

#pragma unroll
        for (int ks = 0; ks < 32; ks += 8) {
            float ah[4][4], al[4][4], bh[4][2], bl[4][2];
#pragma unroll
            for (int mf = 0; mf < 4; mf++) {
                const int ba = (wr * 64 + mf * 16 + tr) * SASTRIDE + ks + tk;
                ah[mf][0] = Ah[ba];
                ah[mf][1] = Ah[ba + 8 * SASTRIDE];
                ah[mf][2] = Ah[ba + 4];
                ah[mf][3] = Ah[ba + 8 * SASTRIDE + 4];
                al[mf][0] = Al[ba];
                al[mf][1] = Al[ba + 8 * SASTRIDE];
                al[mf][2] = Al[ba + 4];
                al[mf][3] = Al[ba + 8 * SASTRIDE + 4];
            }
#pragma unroll
            for (int nf = 0; nf < 4; nf++) {
                const int bb = (wc * 32 + nf * 8 + tr) * SASTRIDE + ks + tk;
                bh[nf][0] = Bh[bb];
                bh[nf][1] = Bh[bb + 4];
                bl[nf][0] = Bl[bb];
                bl[nf][1] = Bl[bb + 4];
            }
#pragma unroll
            for (int mf = 0; mf < 4; mf++)
#pragma unroll
                for (int nf = 0; nf < 4; nf++) {
                    mma_tf32(acc[mf][nf], ah[mf][0], ah[mf][1], ah[mf][2],
                             ah[mf][3], bh[nf][0], bh[nf][1]);
                    mma_tf32(acc[mf][nf], ah[mf][0], ah[mf][1], ah[mf][2],
                             ah[mf][3], bl[nf][0], bl[nf][1]);
                    mma_tf32(acc[mf][nf], al[mf][0], al[mf][1], al[mf][2],
                             al[mf][3], bh[nf][0], bh[nf][1]);
                }
        }
    }

#pragma unroll
    for (int mf = 0; mf < 4; mf++) {
#pragma unroll
        for (int nf = 0; nf < 4; nf++) {
            const int r = row0 + wr * 64 + mf * 16 + tr;
            const int c = col0 + wc * 32 + nf * 8 + 2 * tk;
            float2 o0, o1;
            o0.x = acc[mf][nf][0] + bias[c];
            o0.y = acc[mf][nf][1] + bias[c + 1];
            o1.x = acc[mf][nf][2] + bias[c];
            o1.y = acc[mf][nf][3] + bias[c + 1];
            *(float2*)&C[(size_t)r * DIM + c] = o0;
            *(float2*)&C[(size_t)(r + 8) * DIM + c] = o1;
        }
    }
}

// ---------------------------------------------------------------------------
// Tensor-core flash attention, v3.
// CTA = 128 queries x 1 head, 8 warps; warp = 16 rows x 64-wide tiles.
// B operands (K, V) stored as SINGLE tf32 (rna) in permuted (b0,b1)-pair
// layouts so each fragment is one conflict-free LDS.64; A operands (Q, P)
// are hi/lo split -> 2 MMAs per fragment (B rel err 2^-12 -> output ~1e-5).
//   Ks: pair (K[r][ks*8+tk], K[r][ks*8+tk+4])   at r*72 + (ks*4+tk)*2
//   Vs: pair (V[ks*8+tk][n], V[ks*8+tk+4][n])   at (ks*4+tk)*136 + n*2
// Strides 72 / 136 floats (== 8 mod 32): conflict-free for both patterns.
// ---------------------------------------------------------------------------
#define KS_STRIDE 72
#define VS_STRIDE 136
#define PS_STRIDE 68
#define ATT_SMEM_BYTES ((64 * KS_STRIDE + 32 * VS_STRIDE + 128 * PS_STRIDE) * 4)

__global__ __launch_bounds__(256, 1)
void attn_tc() {
    extern __shared__ float sm[];
    float* Ks = sm;                      // 64 rows x 72
    float* Vs = Ks + 64 * KS_STRIDE;     // 32 krows x 136
    float* Ps = Vs + 32 * VS_STRIDE;     // 128 x 68

    const int h = blockIdx.y;
    const int q0 = blockIdx.x * 128;
    const int tid = threadIdx.x;
    const int w = tid >> 5;
    const int lane = tid & 31;
    const int tr = lane >> 2;
    const int tk = lane & 3;
    const int mrow = w * 16;

    // ---- stage Q tile into Ps (coalesced), then per-warp A fragments ----
#pragma unroll
    for (int j = 0; j < 8; j++) {
        int q4 = tid + j * 256;
        int r = q4 >> 4;
        int c4 = (q4 & 15) * 4;
        *(float4*)&Ps[r * PS_STRIDE + c4] =
            *(const float4*)&g_Q[(size_t)(q0 + r) * DIM + h * HD + c4];
    }
    __syncthreads();

    float qh[8][4], ql[8][4];
#pragma unroll
    for (int ks = 0; ks < 8; ks++) {
        const int ba = (mrow + tr) * PS_STRIDE + ks * 8 + tk;
        float v0 = Ps[ba];
        float v1 = Ps[ba + 8 * PS_STRIDE];
        float v2 = Ps[ba + 4];
        float v3 = Ps[ba + 8 * PS_STRIDE + 4];
        qh[ks][0] = to_tf32(v0); ql[ks][0] = to_tf32(v0 - qh[ks][0]);
        qh[ks][1] = to_tf32(v1); ql[ks][1] = to_tf32(v1 - qh[ks][1]);
        qh[ks][2] = to_tf32(v2); ql[ks][2] = to_tf32(v2 - qh[ks][2]);
        qh[ks][3] = to_tf32(v3); ql[ks][3] = to_tf32(v3 - qh[ks][3]);
    }

    float acc[8][4];
#pragma unroll
    for (int nf = 0; nf < 8; nf++)
#pragma unroll
        for (int i = 0; i < 4; i++) acc[nf][i] = 0.f;
    float l0 = 0.f, l1 = 0.f;

    for (int kt = 0; kt < NKV; kt += 64) {
        __syncthreads();  // previous tile's Ks/Vs reads done
        // ---- cooperative load + single-tf32 convert into pair layouts ----
#pragma unroll
        for (int j = 0; j < 4; j++) {
            int q4 = tid + j * 256;           // 1024 float4 per matrix
            int r = q4 >> 4;                  // 0..63 key row
            int c4 = (q4 & 15) * 4;           // 0..60 col
            float4 kf = *(const float4*)&g_K[(size_t)(kt + r) * DIM + h * HD + c4];
            float4 vf = *(const float4*)&g_V[(size_t)(kt + r) * DIM + h * HD + c4];
            // K: element col c -> Ks[r*72 + ((c>>3)*4 + (c&3))*2 + ((c>>2)&1)]
            {
                const int kbase = r * KS_STRIDE;
#pragma unroll
                for (int i = 0; i < 4; i++) {
                    const int c = c4 + i;
                    const float v = (&kf.x)[i];
                    Ks[kbase + ((c >> 3) * 4 + (c & 3)) * 2 + ((c >> 2) & 1)] =
                        to_tf32(v);
                }
            }
            // V: key row r -> slot row (r>>3)*4 + (r&3), half (r>>2)&1
            {
                const int vbase = ((r >> 3) * 4 + (r & 3)) * VS_STRIDE + ((r >> 2) & 1);
#pragma unroll
                for (int i = 0; i < 4; i++) {
                    Vs[vbase + (c4 + i) * 2] = to_tf32((&vf.x)[i]);
                }
            }
        }
        __syncthreads();

        // ---- phase 1: S = Q @ K^T (A split, B single) ----
        float s[8][4];
#pragma unroll
        for (int nf = 0; nf < 8; nf++)
#pragma unroll
            for (int i = 0; i < 4; i++) s[nf][i] = 0.f;

#pragma unroll
        for (int ks = 0; ks < 8; ks++) {
#pragma unroll
            for (int nf = 0; nf < 8; nf++) {
                float2 B = *(const float2*)
                    &Ks[(nf * 8 + tr) * KS_STRIDE + (ks * 4 + tk) * 2];
                mma_tf32(s[nf], qh[ks][0], qh[ks][1], qh[ks][2], qh[ks][3], B.x, B.y);
                mma_tf32(s[nf], ql[ks][0], ql[ks][1], ql[ks][2], ql[ks][3], B.x, B.y);
            }
        }

        // ---- exp + row-sum + P to smem (own rows only) ----
#pragma unroll
        for (int nf = 0; nf < 8; nf++) {
            float p0 = __expf(s[nf][0] * ATT_SCALE);
            float p1 = __expf(s[nf][1] * ATT_SCALE);
            float p2 = __expf(s[nf][2] * ATT_SCALE);
            float p3 = __expf(s[nf][3] * ATT_SCALE);
            l0 += p0 + p1;
            l1 += p2 + p3;
            float2 w0 = {p0, p1}, w1 = {p2, p3};
            *(float2*)&Ps[(mrow + tr) * PS_STRIDE + nf * 8 + 2 * tk] = w0;
            *(float2*)&Ps[(mrow + tr + 8) * PS_STRIDE + nf * 8 + 2 * tk] = w1;
        }
        __syncwarp();

        // ---- phase 2: O += P @ V (A=P split at read, B=V single) ----
#pragma unroll
        for (int ks = 0; ks < 8; ks++) {
            const int ab = (mrow + tr) * PS_STRIDE + ks * 8 + tk;
            float a0 = Ps[ab];
            float a1 = Ps[ab + 8 * PS_STRIDE];
            float a2 = Ps[ab + 4];
            float a3 = Ps[ab + 8 * PS_STRIDE + 4];
            float ah0 = to_tf32(a0), al0 = a0 - ah0;
            float ah1 = to_tf32(a1), al1 = a1 - ah1;
            float ah2 = to_tf32(a2), al2 = a2 - ah2;
            float ah3 = to_tf32(a3), al3 = a3 - ah3;
#pragma unroll
            for (int nf = 0; nf < 8; nf++) {
                float2 V = *(const float2*)
                    &Vs[(ks * 4 + tk) * VS_STRIDE + (nf * 8 + tr) * 2];
                mma_tf32(acc[nf], ah0, ah1, ah2, ah3, V.x, V.y);
                mma_tf32(acc[nf], al0, al1, al2, al3, V.x, V.y);
            }
        }
    }

    // ---- reduce row sums over the 4 tk lanes, normalize, store ----
    l0 += __shfl_xor_sync(0xFFFFFFFFu, l0, 1);
    l0 += __shfl_xor_sync(0xFFFFFFFFu, l0, 2);
    l1 += __shfl_xor_sync(0xFFFFFFFFu, l1, 1);
    l1 += __shfl_xor_sync(0xFFFFFFFFu, l1, 2);
    const float inv0 = 1.f / l0;
    const float inv1 = 1.f / l1;

    const int r0 = q0 + mrow + tr;
#pragma unroll
    for (int nf = 0; nf < 8; nf++) {
        const int c = h * HD + nf * 8 + 2 * tk;
        float2 o0 = {acc[nf][0] * inv0, acc[nf][1] * inv0};
        float2 o1 = {acc[nf][2] * inv1, acc[nf][3] * inv1};
        *(float2*)&g_AO[(size_t)r0 * DIM + c] = o0;
        *(float2*)&g_AO[(size_t)(r0 + 8) * DIM + c] = o1;
    }
}

// ---------------------------------------------------------------------------
extern "C" void kernel_launch(void* const* d_in, const int* in_sizes, int n_in,
                              void* d_out, int out_size) {
    const float* q   = (const float*)d_in[0];
    const float* kv  = (const float*)d_in[1];
    const float* q_w = (const float*)d_in[2];
    const float* q_b = (const float*)d_in[3];
    const float* k_w = (const float*)d_in[4];
    const float* k_b = (const float*)d_in[5];
    const float* v_w = (const float*)d_in[6];
    const float* v_b = (const float*)d_in[7];
    const float* o_w = (const float*)d_in[8];
    const float* o_b = (const float*)d_in[9];
    float* out = (float*)d_out;

    cudaFuncSetAttribute(gemm_tc, cudaFuncAttributeMaxDynamicSharedMemorySize,
                         GEMM_SMEM_BYTES);
    cudaFuncSetAttribute(attn_tc, cudaFuncAttributeMaxDynamicSharedMemorySize,
                         ATT_SMEM_BYTES);

    dim3 gg(DIM / 128, NQ / 128);
    gemm_tc<<<gg, 256, GEMM_SMEM_BYTES>>>(q,  0, q_w, q_b, nullptr, 0);  // g_Q
    gemm_tc<<<gg, 256, GEMM_SMEM_BYTES>>>(kv, 1, k_w, k_b, nullptr, 1);  // g_K
    gemm_tc<<<gg, 256, GEMM_SMEM_BYTES>>>(kv, 1, v_w, v_b, nullptr, 2);  // g_V

    attn_tc<<<dim3(NQ / 128, NH), 256, ATT_SMEM_BYTES>>>();

    gemm_tc<<<gg, 256, GEMM_SMEM_BYTES>>>(nullptr, 2, o_w, o_b, out, 3); // out
}

// round 12
// speedup vs baseline: 1.5742x; 1.5742x over previous
#include <cuda_runtime.h>
#include <cstdint>

#define DIM 1024
#define NQ 4096
#define NKV 4096
#define NH 16
#define HD 64
#define ATT_SCALE 0.125f  // HD^-0.5

// Scratch (allocation-free rule: __device__ globals)
__device__ float g_Q[NQ * DIM];
__device__ float g_K[NKV * DIM];
__device__ float g_V[NKV * DIM];
__device__ float g_AO[NQ * DIM];

static __device__ __forceinline__ float to_tf32(float x) {
    float r; asm("cvt.rna.tf32.f32 %0, %1;" : "=f"(r) : "f"(x)); return r;
}

static __device__ __forceinline__ void mma_tf32(
    float* c, const float a0, const float a1, const float a2, const float a3,
    const float b0, const float b1) {
    asm volatile(
        "mma.sync.aligned.m16n8k8.row.col.f32.tf32.tf32.f32 "
        "{%0,%1,%2,%3}, {%4,%5,%6,%7}, {%8,%9}, {%0,%1,%2,%3};"
        : "+f"(c[0]), "+f"(c[1]), "+f"(c[2]), "+f"(c[3])
        : "f"(a0), "f"(a1), "f"(a2), "f"(a3), "f"(b0), "f"(b1));
}

// ---------------------------------------------------------------------------
// 3xTF32 mma.sync GEMM: C = X @ W^T + bias  (unchanged — passing, occ 2)
// ---------------------------------------------------------------------------
#define SASTRIDE 36
#define GEMM_SMEM_BYTES (4 * 128 * SASTRIDE * 4)

__global__ __launch_bounds__(256, 2)
void gemm_tc(const float* __restrict__ Xin, int src_tag,
             const float* __restrict__ W,
             const float* __restrict__ bias,
             float* __restrict__ Cout, int dst_tag) {
    extern __shared__ float smf[];
    float* Ah = smf;
    float* Al = Ah + 128 * SASTRIDE;
    float* Bh = Al + 128 * SASTRIDE;
    float* Bl = Bh + 128 * SASTRIDE;

    const float* X = (src_tag == 2) ? g_AO : Xin;
    float* C;
    switch (dst_tag) {
        case 0: C = g_Q; break;
        case 1: C = g_K; break;
        case 2: C = g_V; break;
        default: C = Cout; break;
    }

    const int tid = threadIdx.x;
    const int wid = tid >> 5;
    const int lane = tid & 31;
    const int wr = wid >> 2;
    const int wc = wid & 3;
    const int tr = lane >> 2;
    const int tk = lane & 3;
    const int row0 = blockIdx.y * 128;
    const int col0 = blockIdx.x * 128;

    float acc[4][4][4];
#pragma unroll
    for (int i = 0; i < 4; i++)
#pragma unroll
        for (int j = 0; j < 4; j++)
#pragma unroll
            for (int k = 0; k < 4; k++) acc[i][j][k] = 0.f;

    for (int kb = 0; kb < DIM; kb += 32) {
        __syncthreads();
#pragma unroll
        for (int j = 0; j < 4; j++) {
            const int q = tid + j * 256;
            const int r = q >> 3;
            const int c4 = (q & 7) * 4;
            float4 xv = *(const float4*)&X[(size_t)(row0 + r) * DIM + kb + c4];
            float4 wv = *(const float4*)&W[(size_t)(col0 + r) * DIM + kb + c4];
            float4 h, l;
            h.x = to_tf32(xv.x); l.x = to_tf32(xv.x - h.x);
            h.y = to_tf32(xv.y); l.y = to_tf32(xv.y - h.y);
            h.z = to_tf32(xv.z); l.z = to_tf32(xv.z - h.z);
            h.w = to_tf32(xv.w); l.w = to_tf32(xv.w - h.w);
            *(float4*)&Ah[r * SASTRIDE + c4] = h;
            *(float4*)&Al[r * SASTRIDE + c4] = l;
            h.x = to_tf32(wv.x); l.x = to_tf32(wv.x - h.x);
            h.y = to_tf32(wv.y); l.y = to_tf32(wv.y - h.y);
            h.z = to_tf32(wv.z); l.z = to_tf32(wv.z - h.z);
            h.w = to_tf32(wv.w); l.w = to_tf32(wv.w - h.w);
            *(float4*)&Bh[r * SASTRIDE + c4] = h;
            *(float4*)&Bl[r * SASTRIDE + c4] = l;
        }
        __syncthreads();

#pragma unroll
        for (int ks = 0; ks < 32; ks += 8) {
            float ah[4][4], al[4][4], bh[4][2], bl[4][2];
#pragma unroll
            for (int mf = 0; mf < 4; mf++) {
                const int ba = (wr * 64 + mf * 16 + tr) * SASTRIDE + ks + tk;
                ah[mf][0] = Ah[ba];
                ah[mf][1] = Ah[ba + 8 * SASTRIDE];
                ah[mf][2] = Ah[ba + 4];
                ah[mf][3] = Ah[ba + 8 * SASTRIDE + 4];
                al[mf][0] = Al[ba];
                al[mf][1] = Al[ba + 8 * SASTRIDE];
                al[mf][2] = Al[ba + 4];
                al[mf][3] = Al[ba + 8 * SASTRIDE + 4];
            }
#pragma unroll
            for (int nf = 0; nf < 4; nf++) {
                const int bb = (wc * 32 + nf * 8 + tr) * SASTRIDE + ks + tk;
                bh[nf][0] = Bh[bb];
                bh[nf][1] = Bh[bb + 4];
                bl[nf][0] = Bl[bb];
                bl[nf][1] = Bl[bb + 4];
            }
#pragma unroll
            for (int mf = 0; mf < 4; mf++)
#pragma unroll
                for (int nf = 0; nf < 4; nf++) {
                    mma_tf32(acc[mf][nf], ah[mf][0], ah[mf][1], ah[mf][2],
                             ah[mf][3], bh[nf][0], bh[nf][1]);
                    mma_tf32(acc[mf][nf], ah[mf][0], ah[mf][1], ah[mf][2],
                             ah[mf][3], bl[nf][0], bl[nf][1]);
                    mma_tf32(acc[mf][nf], al[mf][0], al[mf][1], al[mf][2],
                             al[mf][3], bh[nf][0], bh[nf][1]);
                }
        }
    }

#pragma unroll
    for (int mf = 0; mf < 4; mf++) {
#pragma unroll
        for (int nf = 0; nf < 4; nf++) {
            const int r = row0 + wr * 64 + mf * 16 + tr;
            const int c = col0 + wc * 32 + nf * 8 + 2 * tk;
            float2 o0, o1;
            o0.x = acc[mf][nf][0] + bias[c];
            o0.y = acc[mf][nf][1] + bias[c + 1];
            o1.x = acc[mf][nf][2] + bias[c];
            o1.y = acc[mf][nf][3] + bias[c + 1];
            *(float2*)&C[(size_t)r * DIM + c] = o0;
            *(float2*)&C[(size_t)(r + 8) * DIM + c] = o1;
        }
    }
}

// ---------------------------------------------------------------------------
// Tensor-core flash attention, v4 = proven v2 structure, single-tf32 B.
// CTA = 128 queries x 1 head, 8 warps; warp = 16 rows x 64-wide tiles.
// K and V tiles cooperatively pre-split into (hi,lo) interleaved pairs in
// smem with clean float4 stores (identical to the 1433us R9 kernel); the
// only change: the hi*b_lo MMA is dropped in both phases, so B is
// effectively a single rna-tf32 (arithmetic identical to R11's, which
// measured rel_err 2.02e-4 — safely under the 1e-3 gate) and the MMA
// stream shrinks by 1/3.
// ---------------------------------------------------------------------------
#define KV2_STRIDE 136
#define PS_STRIDE 68
#define ATT_SMEM_BYTES ((2 * 64 * KV2_STRIDE + 128 * PS_STRIDE) * 4)

__global__ __launch_bounds__(256, 1)
void attn_tc() {
    extern __shared__ float sm[];
    float* Ks2 = sm;                        // [64][136] (hi,lo) pairs
    float* Vs2 = Ks2 + 64 * KV2_STRIDE;     // [64][136]
    float* Ps  = Vs2 + 64 * KV2_STRIDE;     // [128][68]

    const int h = blockIdx.y;
    const int q0 = blockIdx.x * 128;
    const int tid = threadIdx.x;
    const int w = tid >> 5;
    const int lane = tid & 31;
    const int tr = lane >> 2;
    const int tk = lane & 3;
    const int mrow = w * 16;

    // ---- stage Q tile into Ps (coalesced), then per-warp A fragments ----
#pragma unroll
    for (int j = 0; j < 8; j++) {
        int q4 = tid + j * 256;
        int r = q4 >> 4;
        int c4 = (q4 & 15) * 4;
        *(float4*)&Ps[r * PS_STRIDE + c4] =
            *(const float4*)&g_Q[(size_t)(q0 + r) * DIM + h * HD + c4];
    }
    __syncthreads();

    float qh[8][4], ql[8][4];
#pragma unroll
    for (int ks = 0; ks < 8; ks++) {
        const int ba = (mrow + tr) * PS_STRIDE + ks * 8 + tk;
        float v0 = Ps[ba];
        float v1 = Ps[ba + 8 * PS_STRIDE];
        float v2 = Ps[ba + 4];
        float v3 = Ps[ba + 8 * PS_STRIDE + 4];
        qh[ks][0] = to_tf32(v0); ql[ks][0] = to_tf32(v0 - qh[ks][0]);
        qh[ks][1] = to_tf32(v1); ql[ks][1] = to_tf32(v1 - qh[ks][1]);
        qh[ks][2] = to_tf32(v2); ql[ks][2] = to_tf32(v2 - qh[ks][2]);
        qh[ks][3] = to_tf32(v3); ql[ks][3] = to_tf32(v3 - qh[ks][3]);
    }

    float acc[8][4];
#pragma unroll
    for (int nf = 0; nf < 8; nf++)
#pragma unroll
        for (int i = 0; i < 4; i++) acc[nf][i] = 0.f;
    float l0 = 0.f, l1 = 0.f;

    for (int kt = 0; kt < NKV; kt += 64) {
        __syncthreads();  // previous tile's Ks2/Vs2 reads done
        // ---- cooperative load + tf32 split of K,V: interleaved (h,l) ----
#pragma unroll
        for (int j = 0; j < 4; j++) {
            int q4 = tid + j * 256;           // 1024 float4 per matrix
            int r = q4 >> 4;
            int c4 = (q4 & 15) * 4;
            float4 kf = *(const float4*)&g_K[(size_t)(kt + r) * DIM + h * HD + c4];
            float4 vf = *(const float4*)&g_V[(size_t)(kt + r) * DIM + h * HD + c4];
            float4 p0, p1;
            p0.x = to_tf32(kf.x); p0.y = kf.x - p0.x;
            p0.z = to_tf32(kf.y); p0.w = kf.y - p0.z;
            p1.x = to_tf32(kf.z); p1.y = kf.z - p1.x;
            p1.z = to_tf32(kf.w); p1.w = kf.w - p1.z;
            *(float4*)&Ks2[r * KV2_STRIDE + 2 * c4] = p0;
            *(float4*)&Ks2[r * KV2_STRIDE + 2 * c4 + 4] = p1;
            p0.x = to_tf32(vf.x); p0.y = vf.x - p0.x;
            p0.z = to_tf32(vf.y); p0.w = vf.y - p0.z;
            p1.x = to_tf32(vf.z); p1.y = vf.z - p1.x;
            p1.z = to_tf32(vf.w); p1.w = vf.w - p1.z;
            *(float4*)&Vs2[r * KV2_STRIDE + 2 * c4] = p0;
            *(float4*)&Vs2[r * KV2_STRIDE + 2 * c4 + 4] = p1;
        }
        __syncthreads();

        // ---- phase 1: S = Q @ K^T (A split, B single tf32) ----
        float s[8][4];
#pragma unroll
        for (int nf = 0; nf < 8; nf++)
#pragma unroll
            for (int i = 0; i < 4; i++) s[nf][i] = 0.f;

#pragma unroll
        for (int ks = 0; ks < 8; ks++) {
#pragma unroll
            for (int nf = 0; nf < 8; nf++) {
                const int bb = (nf * 8 + tr) * KV2_STRIDE + 2 * (ks * 8 + tk);
                float2 B0 = *(const float2*)&Ks2[bb];       // (bh0, bl0)
                float2 B1 = *(const float2*)&Ks2[bb + 8];   // (bh1, bl1)
                mma_tf32(s[nf], qh[ks][0], qh[ks][1], qh[ks][2], qh[ks][3], B0.x, B1.x);
                mma_tf32(s[nf], ql[ks][0], ql[ks][1], ql[ks][2], ql[ks][3], B0.x, B1.x);
            }
        }

        // ---- exp + row-sum + P to smem (own rows only) ----
#pragma unroll
        for (int nf = 0; nf < 8; nf++) {
            float p0 = __expf(s[nf][0] * ATT_SCALE);
            float p1 = __expf(s[nf][1] * ATT_SCALE);
            float p2 = __expf(s[nf][2] * ATT_SCALE);
            float p3 = __expf(s[nf][3] * ATT_SCALE);
            l0 += p0 + p1;
            l1 += p2 + p3;
            float2 w0 = {p0, p1}, w1 = {p2, p3};
            *(float2*)&Ps[(mrow + tr) * PS_STRIDE + nf * 8 + 2 * tk] = w0;
            *(float2*)&Ps[(mrow + tr + 8) * PS_STRIDE + nf * 8 + 2 * tk] = w1;
        }
        __syncwarp();

        // ---- phase 2: O += P @ V (A=P split at read, B=V single tf32) ----
#pragma unroll
        for (int ks = 0; ks < 8; ks++) {
            const int ab = (mrow + tr) * PS_STRIDE + ks * 8 + tk;
            float a0 = Ps[ab];
            float a1 = Ps[ab + 8 * PS_STRIDE];
            float a2 = Ps[ab + 4];
            float a3 = Ps[ab + 8 * PS_STRIDE + 4];
            float ah0 = to_tf32(a0), al0 = a0 - ah0;
            float ah1 = to_tf32(a1), al1 = a1 - ah1;
            float ah2 = to_tf32(a2), al2 = a2 - ah2;
            float ah3 = to_tf32(a3), al3 = a3 - ah3;
#pragma unroll
            for (int nf = 0; nf < 8; nf++) {
                const int bb = (ks * 8 + tk) * KV2_STRIDE + 2 * (nf * 8 + tr);
                float2 V0 = *(const float2*)&Vs2[bb];                    // (bh0, bl0)
                float2 V1 = *(const float2*)&Vs2[bb + 4 * KV2_STRIDE];   // (bh1, bl1)
                mma_tf32(acc[nf], ah0, ah1, ah2, ah3, V0.x, V1.x);
                mma_tf32(acc[nf], al0, al1, al2, al3, V0.x, V1.x);
            }
        }
    }

    // ---- reduce row sums over the 4 tk lanes, normalize, store ----
    l0 += __shfl_xor_sync(0xFFFFFFFFu, l0, 1);
    l0 += __shfl_xor_sync(0xFFFFFFFFu, l0, 2);
    l1 += __shfl_xor_sync(0xFFFFFFFFu, l1, 1);
    l1 += __shfl_xor_sync(0xFFFFFFFFu, l1, 2);
    const float inv0 = 1.f / l0;
    const float inv1 = 1.f / l1;

    const int r0 = q0 + mrow + tr;
#pragma unroll
    for (int nf = 0; nf < 8; nf++) {
        const int c = h * HD + nf * 8 + 2 * tk;
        float2 o0 = {acc[nf][0] * inv0, acc[nf][1] * inv0};
        float2 o1 = {acc[nf][2] * inv1, acc[nf][3] * inv1};
        *(float2*)&g_AO[(size_t)r0 * DIM + c] = o0;
        *(float2*)&g_AO[(size_t)(r0 + 8) * DIM + c] = o1;
    }
}

// ---------------------------------------------------------------------------
extern "C" void kernel_launch(void* const* d_in, const int* in_sizes, int n_in,
                              void* d_out, int out_size) {
    const float* q   = (const float*)d_in[0];
    const float* kv  = (const float*)d_in[1];
    const float* q_w = (const float*)d_in[2];
    const float* q_b = (const float*)d_in[3];
    const float* k_w = (const float*)d_in[4];
    const float* k_b = (const float*)d_in[5];
    const float* v_w = (const float*)d_in[6];
    const float* v_b = (const float*)d_in[7];
    const float* o_w = (const float*)d_in[8];
    const float* o_b = (const float*)d_in[9];
    float* out = (float*)d_out;

    cudaFuncSetAttribute(gemm_tc, cudaFuncAttributeMaxDynamicSharedMemorySize,
                         GEMM_SMEM_BYTES);
    cudaFuncSetAttribute(attn_tc, cudaFuncAttributeMaxDynamicSharedMemorySize,
                         ATT_SMEM_BYTES);

    dim3 gg(DIM / 128, NQ / 128);
    gemm_tc<<<gg, 256, GEMM_SMEM_BYTES>>>(q,  0, q_w, q_b, nullptr, 0);  // g_Q
    gemm_tc<<<gg, 256, GEMM_SMEM_BYTES>>>(kv, 1, k_w, k_b, nullptr, 1);  // g_K
    gemm_tc<<<gg, 256, GEMM_SMEM_BYTES>>>(kv, 1, v_w, v_b, nullptr, 2);  // g_V

    attn_tc<<<dim3(NQ / 128, NH), 256, ATT_SMEM_BYTES>>>();

    gemm_tc<<<gg, 256, GEMM_SMEM_BYTES>>>(nullptr, 2, o_w, o_b, out, 3); // out
}

// round 14
// speedup vs baseline: 1.9504x; 1.2389x over previous
#include <cuda_runtime.h>
#include <cstdint>

#define DIM 1024
#define NQ 4096
#define NKV 4096
#define NH 16
#define HD 64
#define ATT_SCALE 0.125f  // HD^-0.5

// Scratch (allocation-free rule: __device__ globals)
__device__ float g_Q[NQ * DIM];
__device__ float g_K[NKV * DIM];
__device__ float g_V[NKV * DIM];
__device__ float g_AO[NQ * DIM];

static __device__ __forceinline__ float to_tf32(float x) {
    float r; asm("cvt.rna.tf32.f32 %0, %1;" : "=f"(r) : "f"(x)); return r;
}

static __device__ __forceinline__ void mma_tf32(
    float* c, const float a0, const float a1, const float a2, const float a3,
    const float b0, const float b1) {
    asm volatile(
        "mma.sync.aligned.m16n8k8.row.col.f32.tf32.tf32.f32 "
        "{%0,%1,%2,%3}, {%4,%5,%6,%7}, {%8,%9}, {%0,%1,%2,%3};"
        : "+f"(c[0]), "+f"(c[1]), "+f"(c[2]), "+f"(c[3])
        : "f"(a0), "f"(a1), "f"(a2), "f"(a3), "f"(b0), "f"(b1));
}

// ---------------------------------------------------------------------------
// 2-term TF32 mma.sync GEMM: C = X @ W^T + bias.
// X hi/lo split (exact), W single rna-tf32: C = (Ah+Al) @ Bh.
// 128x128 CTA tile, 8 warps, warp tile 64x32, BK=32, occ 2.
// ---------------------------------------------------------------------------
#define SASTRIDE 36
#define GEMM_SMEM_BYTES (3 * 128 * SASTRIDE * 4)

__global__ __launch_bounds__(256, 2)
void gemm_tc(const float* __restrict__ Xin, int src_tag,
             const float* __restrict__ W,
             const float* __restrict__ bias,
             float* __restrict__ Cout, int dst_tag) {
    extern __shared__ float smf[];
    float* Ah = smf;
    float* Al = Ah + 128 * SASTRIDE;
    float* Bh = Al + 128 * SASTRIDE;

    const float* X = (src_tag == 2) ? g_AO : Xin;
    float* C;
    switch (dst_tag) {
        case 0: C = g_Q; break;
        case 1: C = g_K; break;
        case 2: C = g_V; break;
        default: C = Cout; break;
    }

    const int tid = threadIdx.x;
    const int wid = tid >> 5;
    const int lane = tid & 31;
    const int wr = wid >> 2;
    const int wc = wid & 3;
    const int tr = lane >> 2;
    const int tk = lane & 3;
    const int row0 = blockIdx.y * 128;
    const int col0 = blockIdx.x * 128;

    float acc[4][4][4];
#pragma unroll
    for (int i = 0; i < 4; i++)
#pragma unroll
        for (int j = 0; j < 4; j++)
#pragma unroll
            for (int k = 0; k < 4; k++) acc[i][j][k] = 0.f;

    for (int kb = 0; kb < DIM; kb += 32) {
        __syncthreads();
#pragma unroll
        for (int j = 0; j < 4; j++) {
            const int q = tid + j * 256;
            const int r = q >> 3;
            const int c4 = (q & 7) * 4;
            float4 xv = *(const float4*)&X[(size_t)(row0 + r) * DIM + kb + c4];
            float4 wv = *(const float4*)&W[(size_t)(col0 + r) * DIM + kb + c4];
            float4 h, l;
            h.x = to_tf32(xv.x); l.x = to_tf32(xv.x - h.x);
            h.y = to_tf32(xv.y); l.y = to_tf32(xv.y - h.y);
            h.z = to_tf32(xv.z); l.z = to_tf32(xv.z - h.z);
            h.w = to_tf32(xv.w); l.w = to_tf32(xv.w - h.w);
            *(float4*)&Ah[r * SASTRIDE + c4] = h;
            *(float4*)&Al[r * SASTRIDE + c4] = l;
            h.x = to_tf32(wv.x);
            h.y = to_tf32(wv.y);
            h.z = to_tf32(wv.z);
            h.w = to_tf32(wv.w);
            *(float4*)&Bh[r * SASTRIDE + c4] = h;
        }
        __syncthreads();

#pragma unroll
        for (int ks = 0; ks < 32; ks += 8) {
            float ah[4][4], al[4][4], bh[4][2];
#pragma unroll
            for (int mf = 0; mf < 4; mf++) {
                const int ba = (wr * 64 + mf * 16 + tr) * SASTRIDE + ks + tk;
                ah[mf][0] = Ah[ba];
                ah[mf][1] = Ah[ba + 8 * SASTRIDE];
                ah[mf][2] = Ah[ba + 4];
                ah[mf][3] = Ah[ba + 8 * SASTRIDE + 4];
                al[mf][0] = Al[ba];
                al[mf][1] = Al[ba + 8 * SASTRIDE];
                al[mf][2] = Al[ba + 4];
                al[mf][3] = Al[ba + 8 * SASTRIDE + 4];
            }
#pragma unroll
            for (int nf = 0; nf < 4; nf++) {
                const int bb = (wc * 32 + nf * 8 + tr) * SASTRIDE + ks + tk;
                bh[nf][0] = Bh[bb];
                bh[nf][1] = Bh[bb + 4];
            }
#pragma unroll
            for (int mf = 0; mf < 4; mf++)
#pragma unroll
                for (int nf = 0; nf < 4; nf++) {
                    mma_tf32(acc[mf][nf], ah[mf][0], ah[mf][1], ah[mf][2],
                             ah[mf][3], bh[nf][0], bh[nf][1]);
                    mma_tf32(acc[mf][nf], al[mf][0], al[mf][1], al[mf][2],
                             al[mf][3], bh[nf][0], bh[nf][1]);
                }
        }
    }

#pragma unroll
    for (int mf = 0; mf < 4; mf++) {
#pragma unroll
        for (int nf = 0; nf < 4; nf++) {
            const int r = row0 + wr * 64 + mf * 16 + tr;
            const int c = col0 + wc * 32 + nf * 8 + 2 * tk;
            float2 o0, o1;
            o0.x = acc[mf][nf][0] + bias[c];
            o0.y = acc[mf][nf][1] + bias[c + 1];
            o1.x = acc[mf][nf][2] + bias[c];
            o1.y = acc[mf][nf][3] + bias[c + 1];
            *(float2*)&C[(size_t)r * DIM + c] = o0;
            *(float2*)&C[(size_t)(r + 8) * DIM + c] = o1;
        }
    }
}

// ---------------------------------------------------------------------------
// Tensor-core flash attention, v5: v4 scheduling with the dead lo-halves
// removed from the K/V smem tiles. K and V stored as SINGLE rna-tf32 in
// the proven R6 unsplit layouts (Ks stride 68, Vs stride 72 — both
// conflict-free). B fragments are 2x LDS.32 -> B smem traffic halves vs
// v4; arithmetic bit-identical to the passing R12 kernel (rel_err 2.0e-4).
// A operands (Q, P) remain hi/lo split -> 2 MMAs per fragment.
// ---------------------------------------------------------------------------
#define KS_STRIDE 68
#define VS_STRIDE 72
#define PS_STRIDE 68
#define ATT_SMEM_BYTES ((64 * KS_STRIDE + 64 * VS_STRIDE + 128 * PS_STRIDE) * 4)

__global__ __launch_bounds__(256, 1)
void attn_tc() {
    extern __shared__ float sm[];
    float* Ks = sm;                      // [64][68] single tf32
    float* Vs = Ks + 64 * KS_STRIDE;     // [64][72] single tf32
    float* Ps = Vs + 64 * VS_STRIDE;     // [128][68]

    const int h = blockIdx.y;
    const int q0 = blockIdx.x * 128;
    const int tid = threadIdx.x;
    const int w = tid >> 5;
    const int lane = tid & 31;
    const int tr = lane >> 2;
    const int tk = lane & 3;
    const int mrow = w * 16;

    // ---- stage Q tile into Ps (coalesced), then per-warp A fragments ----
#pragma unroll
    for (int j = 0; j < 8; j++) {
        int q4 = tid + j * 256;
        int r = q4 >> 4;
        int c4 = (q4 & 15) * 4;
        *(float4*)&Ps[r * PS_STRIDE + c4] =
            *(const float4*)&g_Q[(size_t)(q0 + r) * DIM + h * HD + c4];
    }
    __syncthreads();

    float qh[8][4], ql[8][4];
#pragma unroll
    for (int ks = 0; ks < 8; ks++) {
        const int ba = (mrow + tr) * PS_STRIDE + ks * 8 + tk;
        float v0 = Ps[ba];
        float v1 = Ps[ba + 8 * PS_STRIDE];
        float v2 = Ps[ba + 4];
        float v3 = Ps[ba + 8 * PS_STRIDE + 4];
        qh[ks][0] = to_tf32(v0); ql[ks][0] = to_tf32(v0 - qh[ks][0]);
        qh[ks][1] = to_tf32(v1); ql[ks][1] = to_tf32(v1 - qh[ks][1]);
        qh[ks][2] = to_tf32(v2); ql[ks][2] = to_tf32(v2 - qh[ks][2]);
        qh[ks][3] = to_tf32(v3); ql[ks][3] = to_tf32(v3 - qh[ks][3]);
    }

    float acc[8][4];
#pragma unroll
    for (int nf = 0; nf < 8; nf++)
#pragma unroll
        for (int i = 0; i < 4; i++) acc[nf][i] = 0.f;
    float l0 = 0.f, l1 = 0.f;

    for (int kt = 0; kt < NKV; kt += 64) {
        __syncthreads();  // previous tile's Ks/Vs reads done
        // ---- cooperative load + single rna-tf32 convert ----
#pragma unroll
        for (int j = 0; j < 4; j++) {
            int q4 = tid + j * 256;           // 1024 float4 per matrix
            int r = q4 >> 4;
            int c4 = (q4 & 15) * 4;
            float4 kf = *(const float4*)&g_K[(size_t)(kt + r) * DIM + h * HD + c4];
            float4 vf = *(const float4*)&g_V[(size_t)(kt + r) * DIM + h * HD + c4];
            float4 kq, vq;
            kq.x = to_tf32(kf.x); kq.y = to_tf32(kf.y);
            kq.z = to_tf32(kf.z); kq.w = to_tf32(kf.w);
            vq.x = to_tf32(vf.x); vq.y = to_tf32(vf.y);
            vq.z = to_tf32(vf.z); vq.w = to_tf32(vf.w);
            *(float4*)&Ks[r * KS_STRIDE + c4] = kq;
            *(float4*)&Vs[r * VS_STRIDE + c4] = vq;
        }
        __syncthreads();

        // ---- phase 1: S = Q @ K^T (A split, B single tf32) ----
        float s[8][4];
#pragma unroll
        for (int nf = 0; nf < 8; nf++)
#pragma unroll
            for (int i = 0; i < 4; i++) s[nf][i] = 0.f;

#pragma unroll
        for (int ks = 0; ks < 8; ks++) {
#pragma unroll
            for (int nf = 0; nf < 8; nf++) {
                const int bb = (nf * 8 + tr) * KS_STRIDE + ks * 8 + tk;
                float b0 = Ks[bb];
                float b1 = Ks[bb + 4];
                mma_tf32(s[nf], qh[ks][0], qh[ks][1], qh[ks][2], qh[ks][3], b0, b1);
                mma_tf32(s[nf], ql[ks][0], ql[ks][1], ql[ks][2], ql[ks][3], b0, b1);
            }
        }

        // ---- exp + row-sum + P to smem (own rows only) ----
#pragma unroll
        for (int nf = 0; nf < 8; nf++) {
            float p0 = __expf(s[nf][0] * ATT_SCALE);
            float p1 = __expf(s[nf][1] * ATT_SCALE);
            float p2 = __expf(s[nf][2] * ATT_SCALE);
            float p3 = __expf(s[nf][3] * ATT_SCALE);
            l0 += p0 + p1;
            l1 += p2 + p3;
            float2 w0 = {p0, p1}, w1 = {p2, p3};
            *(float2*)&Ps[(mrow + tr) * PS_STRIDE + nf * 8 + 2 * tk] = w0;
            *(float2*)&Ps[(mrow + tr + 8) * PS_STRIDE + nf * 8 + 2 * tk] = w1;
        }
        __syncwarp();

        // ---- phase 2: O += P @ V (A=P split at read, B=V single tf32) ----
#pragma unroll
        for (int ks = 0; ks < 8; ks++) {
            const int ab = (mrow + tr) * PS_STRIDE + ks * 8 + tk;
            float a0 = Ps[ab];
            float a1 = Ps[ab + 8 * PS_STRIDE];
            float a2 = Ps[ab + 4];
            float a3 = Ps[ab + 8 * PS_STRIDE + 4];
            float ah0 = to_tf32(a0), al0 = a0 - ah0;
            float ah1 = to_tf32(a1), al1 = a1 - ah1;
            float ah2 = to_tf32(a2), al2 = a2 - ah2;
            float ah3 = to_tf32(a3), al3 = a3 - ah3;
#pragma unroll
            for (int nf = 0; nf < 8; nf++) {
                const int bb = (ks * 8 + tk) * VS_STRIDE + nf * 8 + tr;
                float b0 = Vs[bb];
                float b1 = Vs[bb + 4 * VS_STRIDE];
                mma_tf32(acc[nf], ah0, ah1, ah2, ah3, b0, b1);
                mma_tf32(acc[nf], al0, al1, al2, al3, b0, b1);
            }
        }
    }

    // ---- reduce row sums over the 4 tk lanes, normalize, store ----
    l0 += __shfl_xor_sync(0xFFFFFFFFu, l0, 1);
    l0 += __shfl_xor_sync(0xFFFFFFFFu, l0, 2);
    l1 += __shfl_xor_sync(0xFFFFFFFFu, l1, 1);
    l1 += __shfl_xor_sync(0xFFFFFFFFu, l1, 2);
    const float inv0 = 1.f / l0;
    const float inv1 = 1.f / l1;

    const int r0 = q0 + mrow + tr;
#pragma unroll
    for (int nf = 0; nf < 8; nf++) {
        const int c = h * HD + nf * 8 + 2 * tk;
        float2 o0 = {acc[nf][0] * inv0, acc[nf][1] * inv0};
        float2 o1 = {acc[nf][2] * inv1, acc[nf][3] * inv1};
        *(float2*)&g_AO[(size_t)r0 * DIM + c] = o0;
        *(float2*)&g_AO[(size_t)(r0 + 8) * DIM + c] = o1;
    }
}

// ---------------------------------------------------------------------------
extern "C" void kernel_launch(void* const* d_in, const int* in_sizes, int n_in,
                              void* d_out, int out_size) {
    const float* q   = (const float*)d_in[0];
    const float* kv  = (const float*)d_in[1];
    const float* q_w = (const float*)d_in[2];
    const float* q_b = (const float*)d_in[3];
    const float* k_w = (const float*)d_in[4];
    const float* k_b = (const float*)d_in[5];
    const float* v_w = (const float*)d_in[6];
    const float* v_b = (const float*)d_in[7];
    const float* o_w = (const float*)d_in[8];
    const float* o_b = (const float*)d_in[9];
    float* out = (float*)d_out;

    cudaFuncSetAttribute(gemm_tc, cudaFuncAttributeMaxDynamicSharedMemorySize,
                         GEMM_SMEM_BYTES);
    cudaFuncSetAttribute(attn_tc, cudaFuncAttributeMaxDynamicSharedMemorySize,
                         ATT_SMEM_BYTES);

    dim3 gg(DIM / 128, NQ / 128);
    gemm_tc<<<gg, 256, GEMM_SMEM_BYTES>>>(q,  0, q_w, q_b, nullptr, 0);  // g_Q
    gemm_tc<<<gg, 256, GEMM_SMEM_BYTES>>>(kv, 1, k_w, k_b, nullptr, 1);  // g_K
    gemm_tc<<<gg, 256, GEMM_SMEM_BYTES>>>(kv, 1, v_w, v_b, nullptr, 2);  // g_V

    attn_tc<<<dim3(NQ / 128, NH), 256, ATT_SMEM_BYTES>>>();

    gemm_tc<<<gg, 256, GEMM_SMEM_BYTES>>>(nullptr, 2, o_w, o_b, out, 3); // out
}

// round 15
// speedup vs baseline: 2.2497x; 1.1535x over previous
#include <cuda_runtime.h>
#include <cstdint>

#define DIM 1024
#define NQ 4096
#define NKV 4096
#define NH 16
#define HD 64
#define ATT_SCALE 0.125f  // HD^-0.5 == 2^-3 (exact)

// Scratch (allocation-free rule: __device__ globals)
__device__ float g_Q[NQ * DIM];
__device__ float g_K[NKV * DIM];
__device__ float g_V[NKV * DIM];
__device__ float g_AO[NQ * DIM];

static __device__ __forceinline__ float to_tf32(float x) {
    float r; asm("cvt.rna.tf32.f32 %0, %1;" : "=f"(r) : "f"(x)); return r;
}

static __device__ __forceinline__ void mma_tf32(
    float* c, const float a0, const float a1, const float a2, const float a3,
    const float b0, const float b1) {
    asm volatile(
        "mma.sync.aligned.m16n8k8.row.col.f32.tf32.tf32.f32 "
        "{%0,%1,%2,%3}, {%4,%5,%6,%7}, {%8,%9}, {%0,%1,%2,%3};"
        : "+f"(c[0]), "+f"(c[1]), "+f"(c[2]), "+f"(c[3])
        : "f"(a0), "f"(a1), "f"(a2), "f"(a3), "f"(b0), "f"(b1));
}

// ---------------------------------------------------------------------------
// 2-term TF32 mma.sync GEMM: C = X @ W^T + bias.  (unchanged — passing)
// X hi/lo split (exact), W single rna-tf32: C = (Ah+Al) @ Bh.
// ---------------------------------------------------------------------------
#define SASTRIDE 36
#define GEMM_SMEM_BYTES (3 * 128 * SASTRIDE * 4)

__global__ __launch_bounds__(256, 2)
void gemm_tc(const float* __restrict__ Xin, int src_tag,
             const float* __restrict__ W,
             const float* __restrict__ bias,
             float* __restrict__ Cout, int dst_tag) {
    extern __shared__ float smf[];
    float* Ah = smf;
    float* Al = Ah + 128 * SASTRIDE;
    float* Bh = Al + 128 * SASTRIDE;

    const float* X = (src_tag == 2) ? g_AO : Xin;
    float* C;
    switch (dst_tag) {
        case 0: C = g_Q; break;
        case 1: C = g_K; break;
        case 2: C = g_V; break;
        default: C = Cout; break;
    }

    const int tid = threadIdx.x;
    const int wid = tid >> 5;
    const int lane = tid & 31;
    const int wr = wid >> 2;
    const int wc = wid & 3;
    const int tr = lane >> 2;
    const int tk = lane & 3;
    const int row0 = blockIdx.y * 128;
    const int col0 = blockIdx.x * 128;

    float acc[4][4][4];
#pragma unroll
    for (int i = 0; i < 4; i++)
#pragma unroll
        for (int j = 0; j < 4; j++)
#pragma unroll
            for (int k = 0; k < 4; k++) acc[i][j][k] = 0.f;

    for (int kb = 0; kb < DIM; kb += 32) {
        __syncthreads();
#pragma unroll
        for (int j = 0; j < 4; j++) {
            const int q = tid + j * 256;
            const int r = q >> 3;
            const int c4 = (q & 7) * 4;
            float4 xv = *(const float4*)&X[(size_t)(row0 + r) * DIM + kb + c4];
            float4 wv = *(const float4*)&W[(size_t)(col0 + r) * DIM + kb + c4];
            float4 h, l;
            h.x = to_tf32(xv.x); l.x = to_tf32(xv.x - h.x);
            h.y = to_tf32(xv.y); l.y = to_tf32(xv.y - h.y);
            h.z = to_tf32(xv.z); l.z = to_tf32(xv.z - h.z);
            h.w = to_tf32(xv.w); l.w = to_tf32(xv.w - h.w);
            *(float4*)&Ah[r * SASTRIDE + c4] = h;
            *(float4*)&Al[r * SASTRIDE + c4] = l;
            h.x = to_tf32(wv.x);
            h.y = to_tf32(wv.y);
            h.z = to_tf32(wv.z);
            h.w = to_tf32(wv.w);
            *(float4*)&Bh[r * SASTRIDE + c4] = h;
        }
        __syncthreads();

#pragma unroll
        for (int ks = 0; ks < 32; ks += 8) {
            float ah[4][4], al[4][4], bh[4][2];
#pragma unroll
            for (int mf = 0; mf < 4; mf++) {
                const int ba = (wr * 64 + mf * 16 + tr) * SASTRIDE + ks + tk;
                ah[mf][0] = Ah[ba];
                ah[mf][1] = Ah[ba + 8 * SASTRIDE];
                ah[mf][2] = Ah[ba + 4];
                ah[mf][3] = Ah[ba + 8 * SASTRIDE + 4];
                al[mf][0] = Al[ba];
                al[mf][1] = Al[ba + 8 * SASTRIDE];
                al[mf][2] = Al[ba + 4];
                al[mf][3] = Al[ba + 8 * SASTRIDE + 4];
            }
#pragma unroll
            for (int nf = 0; nf < 4; nf++) {
                const int bb = (wc * 32 + nf * 8 + tr) * SASTRIDE + ks + tk;
                bh[nf][0] = Bh[bb];
                bh[nf][1] = Bh[bb + 4];
            }
#pragma unroll
            for (int mf = 0; mf < 4; mf++)
#pragma unroll
                for (int nf = 0; nf < 4; nf++) {
                    mma_tf32(acc[mf][nf], ah[mf][0], ah[mf][1], ah[mf][2],
                             ah[mf][3], bh[nf][0], bh[nf][1]);
                    mma_tf32(acc[mf][nf], al[mf][0], al[mf][1], al[mf][2],
                             al[mf][3], bh[nf][0], bh[nf][1]);
                }
        }
    }

#pragma unroll
    for (int mf = 0; mf < 4; mf++) {
#pragma unroll
        for (int nf = 0; nf < 4; nf++) {
            const int r = row0 + wr * 64 + mf * 16 + tr;
            const int c = col0 + wc * 32 + nf * 8 + 2 * tk;
            float2 o0, o1;
            o0.x = acc[mf][nf][0] + bias[c];
            o0.y = acc[mf][nf][1] + bias[c + 1];
            o1.x = acc[mf][nf][2] + bias[c];
            o1.y = acc[mf][nf][3] + bias[c + 1];
            *(float2*)&C[(size_t)r * DIM + c] = o0;
            *(float2*)&C[(size_t)(r + 8) * DIM + c] = o1;
        }
    }
}

// ---------------------------------------------------------------------------
// Tensor-core flash attention, v6 = v5 with:
//  - Q pre-scaled by ATT_SCALE (2^-3, exact) at staging: no per-S FMUL
//  - phase-2 single-tf32 P (cvt.rna at exp-store): 64 MMAs/tile, no P split
//  - software-pipelined K/V global prefetch (LDG t+1 issued before compute t)
// Layouts identical to v5 (Ks[64][68], Vs[64][72], Ps[128][68]).
// ---------------------------------------------------------------------------
#define KS_STRIDE 68
#define VS_STRIDE 72
#define PS_STRIDE 68
#define ATT_SMEM_BYTES ((64 * KS_STRIDE + 64 * VS_STRIDE + 128 * PS_STRIDE) * 4)

__global__ __launch_bounds__(256, 1)
void attn_tc() {
    extern __shared__ float sm[];
    float* Ks = sm;                      // [64][68] single tf32
    float* Vs = Ks + 64 * KS_STRIDE;     // [64][72] single tf32
    float* Ps = Vs + 64 * VS_STRIDE;     // [128][68]

    const int h = blockIdx.y;
    const int q0 = blockIdx.x * 128;
    const int tid = threadIdx.x;
    const int w = tid >> 5;
    const int lane = tid & 31;
    const int tr = lane >> 2;
    const int tk = lane & 3;
    const int mrow = w * 16;

    // ---- stage Q tile (pre-scaled by 2^-3) into Ps, then A fragments ----
#pragma unroll
    for (int j = 0; j < 8; j++) {
        int q4 = tid + j * 256;
        int r = q4 >> 4;
        int c4 = (q4 & 15) * 4;
        float4 t = *(const float4*)&g_Q[(size_t)(q0 + r) * DIM + h * HD + c4];
        t.x *= ATT_SCALE; t.y *= ATT_SCALE; t.z *= ATT_SCALE; t.w *= ATT_SCALE;
        *(float4*)&Ps[r * PS_STRIDE + c4] = t;
    }
    __syncthreads();

    float qh[8][4], ql[8][4];
#pragma unroll
    for (int ks = 0; ks < 8; ks++) {
        const int ba = (mrow + tr) * PS_STRIDE + ks * 8 + tk;
        float v0 = Ps[ba];
        float v1 = Ps[ba + 8 * PS_STRIDE];
        float v2 = Ps[ba + 4];
        float v3 = Ps[ba + 8 * PS_STRIDE + 4];
        qh[ks][0] = to_tf32(v0); ql[ks][0] = to_tf32(v0 - qh[ks][0]);
        qh[ks][1] = to_tf32(v1); ql[ks][1] = to_tf32(v1 - qh[ks][1]);
        qh[ks][2] = to_tf32(v2); ql[ks][2] = to_tf32(v2 - qh[ks][2]);
        qh[ks][3] = to_tf32(v3); ql[ks][3] = to_tf32(v3 - qh[ks][3]);
    }

    float acc[8][4];
#pragma unroll
    for (int nf = 0; nf < 8; nf++)
#pragma unroll
        for (int i = 0; i < 4; i++) acc[nf][i] = 0.f;
    float l0 = 0.f, l1 = 0.f;

    // ---- prefetch tile 0 into registers ----
    float4 kf[4], vf[4];
    {
        const int r = tid >> 4;
        const int c4 = (tid & 15) * 4;
#pragma unroll
        for (int j = 0; j < 4; j++) {
            kf[j] = *(const float4*)&g_K[(size_t)(j * 16 + r) * DIM + h * HD + c4];
            vf[j] = *(const float4*)&g_V[(size_t)(j * 16 + r) * DIM + h * HD + c4];
        }
    }

    for (int kt = 0; kt < NKV; kt += 64) {
        const int r = tid >> 4;
        const int c4 = (tid & 15) * 4;
        __syncthreads();  // previous tile's Ks/Vs reads done
        // ---- convert + store the prefetched tile ----
#pragma unroll
        for (int j = 0; j < 4; j++) {
            float4 kq, vq;
            kq.x = to_tf32(kf[j].x); kq.y = to_tf32(kf[j].y);
            kq.z = to_tf32(kf[j].z); kq.w = to_tf32(kf[j].w);
            vq.x = to_tf32(vf[j].x); vq.y = to_tf32(vf[j].y);
            vq.z = to_tf32(vf[j].z); vq.w = to_tf32(vf[j].w);
            *(float4*)&Ks[(j * 16 + r) * KS_STRIDE + c4] = kq;
            *(float4*)&Vs[(j * 16 + r) * VS_STRIDE + c4] = vq;
        }
        __syncthreads();

        // ---- prefetch next tile (hidden behind compute below) ----
        if (kt + 64 < NKV) {
#pragma unroll
            for (int j = 0; j < 4; j++) {
                kf[j] = *(const float4*)
                    &g_K[(size_t)(kt + 64 + j * 16 + r) * DIM + h * HD + c4];
                vf[j] = *(const float4*)
                    &g_V[(size_t)(kt + 64 + j * 16 + r) * DIM + h * HD + c4];
            }
        }

        // ---- phase 1: S = Q @ K^T (A split, B single tf32; S pre-scaled) ----
        float s[8][4];
#pragma unroll
        for (int nf = 0; nf < 8; nf++)
#pragma unroll
            for (int i = 0; i < 4; i++) s[nf][i] = 0.f;

#pragma unroll
        for (int ks = 0; ks < 8; ks++) {
#pragma unroll
            for (int nf = 0; nf < 8; nf++) {
                const int bb = (nf * 8 + tr) * KS_STRIDE + ks * 8 + tk;
                float b0 = Ks[bb];
                float b1 = Ks[bb + 4];
                mma_tf32(s[nf], qh[ks][0], qh[ks][1], qh[ks][2], qh[ks][3], b0, b1);
                mma_tf32(s[nf], ql[ks][0], ql[ks][1], ql[ks][2], ql[ks][3], b0, b1);
            }
        }

        // ---- exp + row-sum + tf32 P to smem (own rows only) ----
#pragma unroll
        for (int nf = 0; nf < 8; nf++) {
            float p0 = __expf(s[nf][0]);
            float p1 = __expf(s[nf][1]);
            float p2 = __expf(s[nf][2]);
            float p3 = __expf(s[nf][3]);
            l0 += p0 + p1;
            l1 += p2 + p3;
            float2 w0 = {to_tf32(p0), to_tf32(p1)};
            float2 w1 = {to_tf32(p2), to_tf32(p3)};
            *(float2*)&Ps[(mrow + tr) * PS_STRIDE + nf * 8 + 2 * tk] = w0;
            *(float2*)&Ps[(mrow + tr + 8) * PS_STRIDE + nf * 8 + 2 * tk] = w1;
        }
        __syncwarp();

        // ---- phase 2: O += P @ V (both single tf32) ----
#pragma unroll
        for (int ks = 0; ks < 8; ks++) {
            const int ab = (mrow + tr) * PS_STRIDE + ks * 8 + tk;
            float a0 = Ps[ab];
            float a1 = Ps[ab + 8 * PS_STRIDE];
            float a2 = Ps[ab + 4];
            float a3 = Ps[ab + 8 * PS_STRIDE + 4];
#pragma unroll
            for (int nf = 0; nf < 8; nf++) {
                const int bb = (ks * 8 + tk) * VS_STRIDE + nf * 8 + tr;
                float b0 = Vs[bb];
                float b1 = Vs[bb + 4 * VS_STRIDE];
                mma_tf32(acc[nf], a0, a1, a2, a3, b0, b1);
            }
        }
    }

    // ---- reduce row sums over the 4 tk lanes, normalize, store ----
    l0 += __shfl_xor_sync(0xFFFFFFFFu, l0, 1);
    l0 += __shfl_xor_sync(0xFFFFFFFFu, l0, 2);
    l1 += __shfl_xor_sync(0xFFFFFFFFu, l1, 1);
    l1 += __shfl_xor_sync(0xFFFFFFFFu, l1, 2);
    const float inv0 = 1.f / l0;
    const float inv1 = 1.f / l1;

    const int r0 = q0 + mrow + tr;
#pragma unroll
    for (int nf = 0; nf < 8; nf++) {
        const int c = h * HD + nf * 8 + 2 * tk;
        float2 o0 = {acc[nf][0] * inv0, acc[nf][1] * inv0};
        float2 o1 = {acc[nf][2] * inv1, acc[nf][3] * inv1};
        *(float2*)&g_AO[(size_t)r0 * DIM + c] = o0;
        *(float2*)&g_AO[(size_t)(r0 + 8) * DIM + c] = o1;
    }
}

// ---------------------------------------------------------------------------
extern "C" void kernel_launch(void* const* d_in, const int* in_sizes, int n_in,
                              void* d_out, int out_size) {
    const float* q   = (const float*)d_in[0];
    const float* kv  = (const float*)d_in[1];
    const float* q_w = (const float*)d_in[2];
    const float* q_b = (const float*)d_in[3];
    const float* k_w = (const float*)d_in[4];
    const float* k_b = (const float*)d_in[5];
    const float* v_w = (const float*)d_in[6];
    const float* v_b = (const float*)d_in[7];
    const float* o_w = (const float*)d_in[8];
    const float* o_b = (const float*)d_in[9];
    float* out = (float*)d_out;

    cudaFuncSetAttribute(gemm_tc, cudaFuncAttributeMaxDynamicSharedMemorySize,
                         GEMM_SMEM_BYTES);
    cudaFuncSetAttribute(attn_tc, cudaFuncAttributeMaxDynamicSharedMemorySize,
                         ATT_SMEM_BYTES);

    dim3 gg(DIM / 128, NQ / 128);
    gemm_tc<<<gg, 256, GEMM_SMEM_BYTES>>>(q,  0, q_w, q_b, nullptr, 0);  // g_Q
    gemm_tc<<<gg, 256, GEMM_SMEM_BYTES>>>(kv, 1, k_w, k_b, nullptr, 1);  // g_K
    gemm_tc<<<gg, 256, GEMM_SMEM_BYTES>>>(kv, 1, v_w, v_b, nullptr, 2);  // g_V

    attn_tc<<<dim3(NQ / 128, NH), 256, ATT_SMEM_BYTES>>>();

    gemm_tc<<<gg, 256, GEMM_SMEM_BYTES>>>(nullptr, 2, o_w, o_b, out, 3); // out
}

// round 16
// speedup vs baseline: 2.4893x; 1.1065x over previous
#include <cuda_runtime.h>
#include <cstdint>

#define DIM 1024
#define NQ 4096
#define NKV 4096
#define NH 16
#define HD 64
#define ATT_SCALE 0.125f  // HD^-0.5 == 2^-3 (exact)

// Scratch (allocation-free rule: __device__ globals)
__device__ float g_Q[NQ * DIM];
__device__ float g_K[NKV * DIM];
__device__ float g_V[NKV * DIM];
__device__ float g_AO[NQ * DIM];

static __device__ __forceinline__ float to_tf32(float x) {
    float r; asm("cvt.rna.tf32.f32 %0, %1;" : "=f"(r) : "f"(x)); return r;
}

static __device__ __forceinline__ void mma_tf32(
    float* c, const float a0, const float a1, const float a2, const float a3,
    const float b0, const float b1) {
    asm volatile(
        "mma.sync.aligned.m16n8k8.row.col.f32.tf32.tf32.f32 "
        "{%0,%1,%2,%3}, {%4,%5,%6,%7}, {%8,%9}, {%0,%1,%2,%3};"
        : "+f"(c[0]), "+f"(c[1]), "+f"(c[2]), "+f"(c[3])
        : "f"(a0), "f"(a1), "f"(a2), "f"(a3), "f"(b0), "f"(b1));
}

// ---------------------------------------------------------------------------
// 2-term TF32 mma.sync GEMM: C = X @ W^T + bias.  (unchanged — passing)
// X hi/lo split (exact), W single rna-tf32: C = (Ah+Al) @ Bh.
// ---------------------------------------------------------------------------
#define SASTRIDE 36
#define GEMM_SMEM_BYTES (3 * 128 * SASTRIDE * 4)

__global__ __launch_bounds__(256, 2)
void gemm_tc(const float* __restrict__ Xin, int src_tag,
             const float* __restrict__ W,
             const float* __restrict__ bias,
             float* __restrict__ Cout, int dst_tag) {
    extern __shared__ float smf[];
    float* Ah = smf;
    float* Al = Ah + 128 * SASTRIDE;
    float* Bh = Al + 128 * SASTRIDE;

    const float* X = (src_tag == 2) ? g_AO : Xin;
    float* C;
    switch (dst_tag) {
        case 0: C = g_Q; break;
        case 1: C = g_K; break;
        case 2: C = g_V; break;
        default: C = Cout; break;
    }

    const int tid = threadIdx.x;
    const int wid = tid >> 5;
    const int lane = tid & 31;
    const int wr = wid >> 2;
    const int wc = wid & 3;
    const int tr = lane >> 2;
    const int tk = lane & 3;
    const int row0 = blockIdx.y * 128;
    const int col0 = blockIdx.x * 128;

    float acc[4][4][4];
#pragma unroll
    for (int i = 0; i < 4; i++)
#pragma unroll
        for (int j = 0; j < 4; j++)
#pragma unroll
            for (int k = 0; k < 4; k++) acc[i][j][k] = 0.f;

    for (int kb = 0; kb < DIM; kb += 32) {
        __syncthreads();
#pragma unroll
        for (int j = 0; j < 4; j++) {
            const int q = tid + j * 256;
            const int r = q >> 3;
            const int c4 = (q & 7) * 4;
            float4 xv = *(const float4*)&X[(size_t)(row0 + r) * DIM + kb + c4];
            float4 wv = *(const float4*)&W[(size_t)(col0 + r) * DIM + kb + c4];
            float4 h, l;
            h.x = to_tf32(xv.x); l.x = to_tf32(xv.x - h.x);
            h.y = to_tf32(xv.y); l.y = to_tf32(xv.y - h.y);
            h.z = to_tf32(xv.z); l.z = to_tf32(xv.z - h.z);
            h.w = to_tf32(xv.w); l.w = to_tf32(xv.w - h.w);
            *(float4*)&Ah[r * SASTRIDE + c4] = h;
            *(float4*)&Al[r * SASTRIDE + c4] = l;
            h.x = to_tf32(wv.x);
            h.y = to_tf32(wv.y);
            h.z = to_tf32(wv.z);
            h.w = to_tf32(wv.w);
            *(float4*)&Bh[r * SASTRIDE + c4] = h;
        }
        __syncthreads();

#pragma unroll
        for (int ks = 0; ks < 32; ks += 8) {
            float ah[4][4], al[4][4], bh[4][2];
#pragma unroll
            for (int mf = 0; mf < 4; mf++) {
                const int ba = (wr * 64 + mf * 16 + tr) * SASTRIDE + ks + tk;
                ah[mf][0] = Ah[ba];
                ah[mf][1] = Ah[ba + 8 * SASTRIDE];
                ah[mf][2] = Ah[ba + 4];
                ah[mf][3] = Ah[ba + 8 * SASTRIDE + 4];
                al[mf][0] = Al[ba];
                al[mf][1] = Al[ba + 8 * SASTRIDE];
                al[mf][2] = Al[ba + 4];
                al[mf][3] = Al[ba + 8 * SASTRIDE + 4];
            }
#pragma unroll
            for (int nf = 0; nf < 4; nf++) {
                const int bb = (wc * 32 + nf * 8 + tr) * SASTRIDE + ks + tk;
                bh[nf][0] = Bh[bb];
                bh[nf][1] = Bh[bb + 4];
            }
#pragma unroll
            for (int mf = 0; mf < 4; mf++)
#pragma unroll
                for (int nf = 0; nf < 4; nf++) {
                    mma_tf32(acc[mf][nf], ah[mf][0], ah[mf][1], ah[mf][2],
                             ah[mf][3], bh[nf][0], bh[nf][1]);
                    mma_tf32(acc[mf][nf], al[mf][0], al[mf][1], al[mf][2],
                             al[mf][3], bh[nf][0], bh[nf][1]);
                }
        }
    }

#pragma unroll
    for (int mf = 0; mf < 4; mf++) {
#pragma unroll
        for (int nf = 0; nf < 4; nf++) {
            const int r = row0 + wr * 64 + mf * 16 + tr;
            const int c = col0 + wc * 32 + nf * 8 + 2 * tk;
            float2 o0, o1;
            o0.x = acc[mf][nf][0] + bias[c];
            o0.y = acc[mf][nf][1] + bias[c + 1];
            o1.x = acc[mf][nf][2] + bias[c];
            o1.y = acc[mf][nf][3] + bias[c + 1];
            *(float2*)&C[(size_t)r * DIM + c] = o0;
            *(float2*)&C[(size_t)(r + 8) * DIM + c] = o1;
        }
    }
}

// ---------------------------------------------------------------------------
// Tensor-core flash attention, v7 = v6 with single-tf32 Q in phase 1.
// All operands of both MMA phases are now single rna-tf32 (Q pre-scaled by
// 2^-3 exact); 128 MMAs per warp-tile (was 192). Prefetch, layouts,
// prescale, P/V handling identical to the passing R15 kernel.
// ---------------------------------------------------------------------------
#define KS_STRIDE 68
#define VS_STRIDE 72
#define PS_STRIDE 68
#define ATT_SMEM_BYTES ((64 * KS_STRIDE + 64 * VS_STRIDE + 128 * PS_STRIDE) * 4)

__global__ __launch_bounds__(256, 1)
void attn_tc() {
    extern __shared__ float sm[];
    float* Ks = sm;                      // [64][68] single tf32
    float* Vs = Ks + 64 * KS_STRIDE;     // [64][72] single tf32
    float* Ps = Vs + 64 * VS_STRIDE;     // [128][68]

    const int h = blockIdx.y;
    const int q0 = blockIdx.x * 128;
    const int tid = threadIdx.x;
    const int w = tid >> 5;
    const int lane = tid & 31;
    const int tr = lane >> 2;
    const int tk = lane & 3;
    const int mrow = w * 16;

    // ---- stage Q tile (pre-scaled by 2^-3) into Ps, then A fragments ----
#pragma unroll
    for (int j = 0; j < 8; j++) {
        int q4 = tid + j * 256;
        int r = q4 >> 4;
        int c4 = (q4 & 15) * 4;
        float4 t = *(const float4*)&g_Q[(size_t)(q0 + r) * DIM + h * HD + c4];
        t.x *= ATT_SCALE; t.y *= ATT_SCALE; t.z *= ATT_SCALE; t.w *= ATT_SCALE;
        *(float4*)&Ps[r * PS_STRIDE + c4] = t;
    }
    __syncthreads();

    float qh[8][4];
#pragma unroll
    for (int ks = 0; ks < 8; ks++) {
        const int ba = (mrow + tr) * PS_STRIDE + ks * 8 + tk;
        qh[ks][0] = to_tf32(Ps[ba]);
        qh[ks][1] = to_tf32(Ps[ba + 8 * PS_STRIDE]);
        qh[ks][2] = to_tf32(Ps[ba + 4]);
        qh[ks][3] = to_tf32(Ps[ba + 8 * PS_STRIDE + 4]);
    }

    float acc[8][4];
#pragma unroll
    for (int nf = 0; nf < 8; nf++)
#pragma unroll
        for (int i = 0; i < 4; i++) acc[nf][i] = 0.f;
    float l0 = 0.f, l1 = 0.f;

    // ---- prefetch tile 0 into registers ----
    float4 kf[4], vf[4];
    {
        const int r = tid >> 4;
        const int c4 = (tid & 15) * 4;
#pragma unroll
        for (int j = 0; j < 4; j++) {
            kf[j] = *(const float4*)&g_K[(size_t)(j * 16 + r) * DIM + h * HD + c4];
            vf[j] = *(const float4*)&g_V[(size_t)(j * 16 + r) * DIM + h * HD + c4];
        }
    }

    for (int kt = 0; kt < NKV; kt += 64) {
        const int r = tid >> 4;
        const int c4 = (tid & 15) * 4;
        __syncthreads();  // previous tile's Ks/Vs reads done
        // ---- convert + store the prefetched tile ----
#pragma unroll
        for (int j = 0; j < 4; j++) {
            float4 kq, vq;
            kq.x = to_tf32(kf[j].x); kq.y = to_tf32(kf[j].y);
            kq.z = to_tf32(kf[j].z); kq.w = to_tf32(kf[j].w);
            vq.x = to_tf32(vf[j].x); vq.y = to_tf32(vf[j].y);
            vq.z = to_tf32(vf[j].z); vq.w = to_tf32(vf[j].w);
            *(float4*)&Ks[(j * 16 + r) * KS_STRIDE + c4] = kq;
            *(float4*)&Vs[(j * 16 + r) * VS_STRIDE + c4] = vq;
        }
        __syncthreads();

        // ---- prefetch next tile (hidden behind compute below) ----
        if (kt + 64 < NKV) {
#pragma unroll
            for (int j = 0; j < 4; j++) {
                kf[j] = *(const float4*)
                    &g_K[(size_t)(kt + 64 + j * 16 + r) * DIM + h * HD + c4];
                vf[j] = *(const float4*)
                    &g_V[(size_t)(kt + 64 + j * 16 + r) * DIM + h * HD + c4];
            }
        }

        // ---- phase 1: S = Q @ K^T (both single tf32; S pre-scaled) ----
        float s[8][4];
#pragma unroll
        for (int nf = 0; nf < 8; nf++)
#pragma unroll
            for (int i = 0; i < 4; i++) s[nf][i] = 0.f;

#pragma unroll
        for (int ks = 0; ks < 8; ks++) {
#pragma unroll
            for (int nf = 0; nf < 8; nf++) {
                const int bb = (nf * 8 + tr) * KS_STRIDE + ks * 8 + tk;
                float b0 = Ks[bb];
                float b1 = Ks[bb + 4];
                mma_tf32(s[nf], qh[ks][0], qh[ks][1], qh[ks][2], qh[ks][3], b0, b1);
            }
        }

        // ---- exp + row-sum + tf32 P to smem (own rows only) ----
#pragma unroll
        for (int nf = 0; nf < 8; nf++) {
            float p0 = __expf(s[nf][0]);
            float p1 = __expf(s[nf][1]);
            float p2 = __expf(s[nf][2]);
            float p3 = __expf(s[nf][3]);
            l0 += p0 + p1;
            l1 += p2 + p3;
            float2 w0 = {to_tf32(p0), to_tf32(p1)};
            float2 w1 = {to_tf32(p2), to_tf32(p3)};
            *(float2*)&Ps[(mrow + tr) * PS_STRIDE + nf * 8 + 2 * tk] = w0;
            *(float2*)&Ps[(mrow + tr + 8) * PS_STRIDE + nf * 8 + 2 * tk] = w1;
        }
        __syncwarp();

        // ---- phase 2: O += P @ V (both single tf32) ----
#pragma unroll
        for (int ks = 0; ks < 8; ks++) {
            const int ab = (mrow + tr) * PS_STRIDE + ks * 8 + tk;
            float a0 = Ps[ab];
            float a1 = Ps[ab + 8 * PS_STRIDE];
            float a2 = Ps[ab + 4];
            float a3 = Ps[ab + 8 * PS_STRIDE + 4];
#pragma unroll
            for (int nf = 0; nf < 8; nf++) {
                const int bb = (ks * 8 + tk) * VS_STRIDE + nf * 8 + tr;
                float b0 = Vs[bb];
                float b1 = Vs[bb + 4 * VS_STRIDE];
                mma_tf32(acc[nf], a0, a1, a2, a3, b0, b1);
            }
        }
    }

    // ---- reduce row sums over the 4 tk lanes, normalize, store ----
    l0 += __shfl_xor_sync(0xFFFFFFFFu, l0, 1);
    l0 += __shfl_xor_sync(0xFFFFFFFFu, l0, 2);
    l1 += __shfl_xor_sync(0xFFFFFFFFu, l1, 1);
    l1 += __shfl_xor_sync(0xFFFFFFFFu, l1, 2);
    const float inv0 = 1.f / l0;
    const float inv1 = 1.f / l1;

    const int r0 = q0 + mrow + tr;
#pragma unroll
    for (int nf = 0; nf < 8; nf++) {
        const int c = h * HD + nf * 8 + 2 * tk;
        float2 o0 = {acc[nf][0] * inv0, acc[nf][1] * inv0};
        float2 o1 = {acc[nf][2] * inv1, acc[nf][3] * inv1};
        *(float2*)&g_AO[(size_t)r0 * DIM + c] = o0;
        *(float2*)&g_AO[(size_t)(r0 + 8) * DIM + c] = o1;
    }
}

// ---------------------------------------------------------------------------
extern "C" void kernel_launch(void* const* d_in, const int* in_sizes, int n_in,
                              void* d_out, int out_size) {
    const float* q   = (const float*)d_in[0];
    const float* kv  = (const float*)d_in[1];
    const float* q_w = (const float*)d_in[2];
    const float* q_b = (const float*)d_in[3];
    const float* k_w = (const float*)d_in[4];
    const float* k_b = (const float*)d_in[5];
    const float* v_w = (const float*)d_in[6];
    const float* v_b = (const float*)d_in[7];
    const float* o_w = (const float*)d_in[8];
    const float* o_b = (const float*)d_in[9];
    float* out = (float*)d_out;

    cudaFuncSetAttribute(gemm_tc, cudaFuncAttributeMaxDynamicSharedMemorySize,
                         GEMM_SMEM_BYTES);
    cudaFuncSetAttribute(attn_tc, cudaFuncAttributeMaxDynamicSharedMemorySize,
                         ATT_SMEM_BYTES);

    dim3 gg(DIM / 128, NQ / 128);
    gemm_tc<<<gg, 256, GEMM_SMEM_BYTES>>>(q,  0, q_w, q_b, nullptr, 0);  // g_Q
    gemm_tc<<<gg, 256, GEMM_SMEM_BYTES>>>(kv, 1, k_w, k_b, nullptr, 1);  // g_K
    gemm_tc<<<gg, 256, GEMM_SMEM_BYTES>>>(kv, 1, v_w, v_b, nullptr, 2);  // g_V

    attn_tc<<<dim3(NQ / 128, NH), 256, ATT_SMEM_BYTES>>>();

    gemm_tc<<<gg, 256, GEMM_SMEM_BYTES>>>(nullptr, 2, o_w, o_b, out, 3); // out
}

// round 17
// speedup vs baseline: 2.9064x; 1.1676x over previous
#include <cuda_runtime.h>
#include <cstdint>

#define DIM 1024
#define NQ 4096
#define NKV 4096
#define NH 16
#define HD 64
#define ATT_SCALE 0.125f  // HD^-0.5 == 2^-3 (exact)

// Scratch (allocation-free rule: __device__ globals)
__device__ float g_Q[NQ * DIM];
__device__ float g_K[NKV * DIM];
__device__ float g_V[NKV * DIM];
__device__ float g_AO[NQ * DIM];

static __device__ __forceinline__ float to_tf32(float x) {
    float r; asm("cvt.rna.tf32.f32 %0, %1;" : "=f"(r) : "f"(x)); return r;
}

static __device__ __forceinline__ void mma_tf32(
    float* c, const float a0, const float a1, const float a2, const float a3,
    const float b0, const float b1) {
    asm volatile(
        "mma.sync.aligned.m16n8k8.row.col.f32.tf32.tf32.f32 "
        "{%0,%1,%2,%3}, {%4,%5,%6,%7}, {%8,%9}, {%0,%1,%2,%3};"
        : "+f"(c[0]), "+f"(c[1]), "+f"(c[2]), "+f"(c[3])
        : "f"(a0), "f"(a1), "f"(a2), "f"(a3), "f"(b0), "f"(b1));
}

// ---------------------------------------------------------------------------
// Single-tf32 mma.sync GEMM: C = tf32(X) @ tf32(W)^T + bias (fp32 accum).
// 128x128 CTA tile, 8 warps, warp tile 64x32, BK=32, occ 2.
// Al (X-lo path) removed vs R16: -40% fragment loads, -33% stores, -50% MMAs.
// ---------------------------------------------------------------------------
#define SASTRIDE 36
#define GEMM_SMEM_BYTES (2 * 128 * SASTRIDE * 4)

__global__ __launch_bounds__(256, 2)
void gemm_tc(const float* __restrict__ Xin, int src_tag,
             const float* __restrict__ W,
             const float* __restrict__ bias,
             float* __restrict__ Cout, int dst_tag) {
    extern __shared__ float smf[];
    float* Ah = smf;
    float* Bh = Ah + 128 * SASTRIDE;

    const float* X = (src_tag == 2) ? g_AO : Xin;
    float* C;
    switch (dst_tag) {
        case 0: C = g_Q; break;
        case 1: C = g_K; break;
        case 2: C = g_V; break;
        default: C = Cout; break;
    }

    const int tid = threadIdx.x;
    const int wid = tid >> 5;
    const int lane = tid & 31;
    const int wr = wid >> 2;
    const int wc = wid & 3;
    const int tr = lane >> 2;
    const int tk = lane & 3;
    const int row0 = blockIdx.y * 128;
    const int col0 = blockIdx.x * 128;

    float acc[4][4][4];
#pragma unroll
    for (int i = 0; i < 4; i++)
#pragma unroll
        for (int j = 0; j < 4; j++)
#pragma unroll
            for (int k = 0; k < 4; k++) acc[i][j][k] = 0.f;

    for (int kb = 0; kb < DIM; kb += 32) {
        __syncthreads();
#pragma unroll
        for (int j = 0; j < 4; j++) {
            const int q = tid + j * 256;
            const int r = q >> 3;
            const int c4 = (q & 7) * 4;
            float4 xv = *(const float4*)&X[(size_t)(row0 + r) * DIM + kb + c4];
            float4 wv = *(const float4*)&W[(size_t)(col0 + r) * DIM + kb + c4];
            float4 h;
            h.x = to_tf32(xv.x);
            h.y = to_tf32(xv.y);
            h.z = to_tf32(xv.z);
            h.w = to_tf32(xv.w);
            *(float4*)&Ah[r * SASTRIDE + c4] = h;
            h.x = to_tf32(wv.x);
            h.y = to_tf32(wv.y);
            h.z = to_tf32(wv.z);
            h.w = to_tf32(wv.w);
            *(float4*)&Bh[r * SASTRIDE + c4] = h;
        }
        __syncthreads();

#pragma unroll
        for (int ks = 0; ks < 32; ks += 8) {
            float ah[4][4], bh[4][2];
#pragma unroll
            for (int mf = 0; mf < 4; mf++) {
                const int ba = (wr * 64 + mf * 16 + tr) * SASTRIDE + ks + tk;
                ah[mf][0] = Ah[ba];
                ah[mf][1] = Ah[ba + 8 * SASTRIDE];
                ah[mf][2] = Ah[ba + 4];
                ah[mf][3] = Ah[ba + 8 * SASTRIDE + 4];
            }
#pragma unroll
            for (int nf = 0; nf < 4; nf++) {
                const int bb = (wc * 32 + nf * 8 + tr) * SASTRIDE + ks + tk;
                bh[nf][0] = Bh[bb];
                bh[nf][1] = Bh[bb + 4];
            }
#pragma unroll
            for (int mf = 0; mf < 4; mf++)
#pragma unroll
                for (int nf = 0; nf < 4; nf++) {
                    mma_tf32(acc[mf][nf], ah[mf][0], ah[mf][1], ah[mf][2],
                             ah[mf][3], bh[nf][0], bh[nf][1]);
                }
        }
    }

#pragma unroll
    for (int mf = 0; mf < 4; mf++) {
#pragma unroll
        for (int nf = 0; nf < 4; nf++) {
            const int r = row0 + wr * 64 + mf * 16 + tr;
            const int c = col0 + wc * 32 + nf * 8 + 2 * tk;
            float2 o0, o1;
            o0.x = acc[mf][nf][0] + bias[c];
            o0.y = acc[mf][nf][1] + bias[c + 1];
            o1.x = acc[mf][nf][2] + bias[c];
            o1.y = acc[mf][nf][3] + bias[c + 1];
            *(float2*)&C[(size_t)r * DIM + c] = o0;
            *(float2*)&C[(size_t)(r + 8) * DIM + c] = o1;
        }
    }
}

// ---------------------------------------------------------------------------
// Tensor-core flash attention, v7 (unchanged from passing R16 kernel).
// All MMA operands single rna-tf32; Q pre-scaled by 2^-3 (exact);
// software-pipelined K/V register prefetch.
// ---------------------------------------------------------------------------
#define KS_STRIDE 68
#define VS_STRIDE 72
#define PS_STRIDE 68
#define ATT_SMEM_BYTES ((64 * KS_STRIDE + 64 * VS_STRIDE + 128 * PS_STRIDE) * 4)

__global__ __launch_bounds__(256, 1)
void attn_tc() {
    extern __shared__ float sm[];
    float* Ks = sm;                      // [64][68] single tf32
    float* Vs = Ks + 64 * KS_STRIDE;     // [64][72] single tf32
    float* Ps = Vs + 64 * VS_STRIDE;     // [128][68]

    const int h = blockIdx.y;
    const int q0 = blockIdx.x * 128;
    const int tid = threadIdx.x;
    const int w = tid >> 5;
    const int lane = tid & 31;
    const int tr = lane >> 2;
    const int tk = lane & 3;
    const int mrow = w * 16;

    // ---- stage Q tile (pre-scaled by 2^-3) into Ps, then A fragments ----
#pragma unroll
    for (int j = 0; j < 8; j++) {
        int q4 = tid + j * 256;
        int r = q4 >> 4;
        int c4 = (q4 & 15) * 4;
        float4 t = *(const float4*)&g_Q[(size_t)(q0 + r) * DIM + h * HD + c4];
        t.x *= ATT_SCALE; t.y *= ATT_SCALE; t.z *= ATT_SCALE; t.w *= ATT_SCALE;
        *(float4*)&Ps[r * PS_STRIDE + c4] = t;
    }
    __syncthreads();

    float qh[8][4];
#pragma unroll
    for (int ks = 0; ks < 8; ks++) {
        const int ba = (mrow + tr) * PS_STRIDE + ks * 8 + tk;
        qh[ks][0] = to_tf32(Ps[ba]);
        qh[ks][1] = to_tf32(Ps[ba + 8 * PS_STRIDE]);
        qh[ks][2] = to_tf32(Ps[ba + 4]);
        qh[ks][3] = to_tf32(Ps[ba + 8 * PS_STRIDE + 4]);
    }

    float acc[8][4];
#pragma unroll
    for (int nf = 0; nf < 8; nf++)
#pragma unroll
        for (int i = 0; i < 4; i++) acc[nf][i] = 0.f;
    float l0 = 0.f, l1 = 0.f;

    // ---- prefetch tile 0 into registers ----
    float4 kf[4], vf[4];
    {
        const int r = tid >> 4;
        const int c4 = (tid & 15) * 4;
#pragma unroll
        for (int j = 0; j < 4; j++) {
            kf[j] = *(const float4*)&g_K[(size_t)(j * 16 + r) * DIM + h * HD + c4];
            vf[j] = *(const float4*)&g_V[(size_t)(j * 16 + r) * DIM + h * HD + c4];
        }
    }

    for (int kt = 0; kt < NKV; kt += 64) {
        const int r = tid >> 4;
        const int c4 = (tid & 15) * 4;
        __syncthreads();  // previous tile's Ks/Vs reads done
        // ---- convert + store the prefetched tile ----
#pragma unroll
        for (int j = 0; j < 4; j++) {
            float4 kq, vq;
            kq.x = to_tf32(kf[j].x); kq.y = to_tf32(kf[j].y);
            kq.z = to_tf32(kf[j].z); kq.w = to_tf32(kf[j].w);
            vq.x = to_tf32(vf[j].x); vq.y = to_tf32(vf[j].y);
            vq.z = to_tf32(vf[j].z); vq.w = to_tf32(vf[j].w);
            *(float4*)&Ks[(j * 16 + r) * KS_STRIDE + c4] = kq;
            *(float4*)&Vs[(j * 16 + r) * VS_STRIDE + c4] = vq;
        }
        __syncthreads();

        // ---- prefetch next tile (hidden behind compute below) ----
        if (kt + 64 < NKV) {
#pragma unroll
            for (int j = 0; j < 4; j++) {
                kf[j] = *(const float4*)
                    &g_K[(size_t)(kt + 64 + j * 16 + r) * DIM + h * HD + c4];
                vf[j] = *(const float4*)
                    &g_V[(size_t)(kt + 64 + j * 16 + r) * DIM + h * HD + c4];
            }
        }

        // ---- phase 1: S = Q @ K^T (both single tf32; S pre-scaled) ----
        float s[8][4];
#pragma unroll
        for (int nf = 0; nf < 8; nf++)
#pragma unroll
            for (int i = 0; i < 4; i++) s[nf][i] = 0.f;

#pragma unroll
        for (int ks = 0; ks < 8; ks++) {
#pragma unroll
            for (int nf = 0; nf < 8; nf++) {
                const int bb = (nf * 8 + tr) * KS_STRIDE + ks * 8 + tk;
                float b0 = Ks[bb];
                float b1 = Ks[bb + 4];
                mma_tf32(s[nf], qh[ks][0], qh[ks][1], qh[ks][2], qh[ks][3], b0, b1);
            }
        }

        // ---- exp + row-sum + tf32 P to smem (own rows only) ----
#pragma unroll
        for (int nf = 0; nf < 8; nf++) {
            float p0 = __expf(s[nf][0]);
            float p1 = __expf(s[nf][1]);
            float p2 = __expf(s[nf][2]);
            float p3 = __expf(s[nf][3]);
            l0 += p0 + p1;
            l1 += p2 + p3;
            float2 w0 = {to_tf32(p0), to_tf32(p1)};
            float2 w1 = {to_tf32(p2), to_tf32(p3)};
            *(float2*)&Ps[(mrow + tr) * PS_STRIDE + nf * 8 + 2 * tk] = w0;
            *(float2*)&Ps[(mrow + tr + 8) * PS_STRIDE + nf * 8 + 2 * tk] = w1;
        }
        __syncwarp();

        // ---- phase 2: O += P @ V (both single tf32) ----
#pragma unroll
        for (int ks = 0; ks < 8; ks++) {
            const int ab = (mrow + tr) * PS_STRIDE + ks * 8 + tk;
            float a0 = Ps[ab];
            float a1 = Ps[ab + 8 * PS_STRIDE];
            float a2 = Ps[ab + 4];
            float a3 = Ps[ab + 8 * PS_STRIDE + 4];
#pragma unroll
            for (int nf = 0; nf < 8; nf++) {
                const int bb = (ks * 8 + tk) * VS_STRIDE + nf * 8 + tr;
                float b0 = Vs[bb];
                float b1 = Vs[bb + 4 * VS_STRIDE];
                mma_tf32(acc[nf], a0, a1, a2, a3, b0, b1);
            }
        }
    }

    // ---- reduce row sums over the 4 tk lanes, normalize, store ----
    l0 += __shfl_xor_sync(0xFFFFFFFFu, l0, 1);
    l0 += __shfl_xor_sync(0xFFFFFFFFu, l0, 2);
    l1 += __shfl_xor_sync(0xFFFFFFFFu, l1, 1);
    l1 += __shfl_xor_sync(0xFFFFFFFFu, l1, 2);
    const float inv0 = 1.f / l0;
    const float inv1 = 1.f / l1;

    const int r0 = q0 + mrow + tr;
#pragma unroll
    for (int nf = 0; nf < 8; nf++) {
        const int c = h * HD + nf * 8 + 2 * tk;
        float2 o0 = {acc[nf][0] * inv0, acc[nf][1] * inv0};
        float2 o1 = {acc[nf][2] * inv1, acc[nf][3] * inv1};
        *(float2*)&g_AO[(size_t)r0 * DIM + c] = o0;
        *(float2*)&g_AO[(size_t)(r0 + 8) * DIM + c] = o1;
    }
}

// ---------------------------------------------------------------------------
extern "C" void kernel_launch(void* const* d_in, const int* in_sizes, int n_in,
                              void* d_out, int out_size) {
    const float* q   = (const float*)d_in[0];
    const float* kv  = (const float*)d_in[1];
    const float* q_w = (const float*)d_in[2];
    const float* q_b = (const float*)d_in[3];
    const float* k_w = (const float*)d_in[4];
    const float* k_b = (const float*)d_in[5];
    const float* v_w = (const float*)d_in[6];
    const float* v_b = (const float*)d_in[7];
    const float* o_w = (const float*)d_in[8];
    const float* o_b = (const float*)d_in[9];
    float* out = (float*)d_out;

    cudaFuncSetAttribute(gemm_tc, cudaFuncAttributeMaxDynamicSharedMemorySize,
                         GEMM_SMEM_BYTES);
    cudaFuncSetAttribute(attn_tc, cudaFuncAttributeMaxDynamicSharedMemorySize,
                         ATT_SMEM_BYTES);

    dim3 gg(DIM / 128, NQ / 128);
    gemm_tc<<<gg, 256, GEMM_SMEM_BYTES>>>(q,  0, q_w, q_b, nullptr, 0);  // g_Q
    gemm_tc<<<gg, 256, GEMM_SMEM_BYTES>>>(kv, 1, k_w, k_b, nullptr, 1);  // g_K
    gemm_tc<<<gg, 256, GEMM_SMEM_BYTES>>>(kv, 1, v_w, v_b, nullptr, 2);  // g_V

    attn_tc<<<dim3(NQ / 128, NH), 256, ATT_SMEM_BYTES>>>();

    gemm_tc<<<gg, 256, GEMM_SMEM_BYTES>>>(nullptr, 2, o_w, o_b, out, 3); // out
}